// round 2
// baseline (speedup 1.0000x reference)
#include <cuda_runtime.h>
#include <math.h>

#define BB 65536
#define KK 256
#define DD 128

typedef unsigned long long u64;

// ---- scratch (static device globals; no allocation) ----
__device__ float g_K[(size_t)BB * KK];   // K' = exp(-C/eps) + 1e-8   (64MB) — must stay L2-resident
__device__ float g_ynT[DD * KK];         // normalized prototypes, k-major [k][j]
__device__ float g_xinv[BB];             // 1 / ||x_i||
__device__ float g_a[BB];                // exp(u)
__device__ float g_T[3][KK * 32];        // column sums, padded 128B apart
__device__ double g_sum;

// packed fp32x2 FMA (sm_103a FFMA2): d = a*b + d on both lanes
__device__ __forceinline__ void fma2(u64& d, u64 a, u64 b) {
    asm("fma.rn.f32x2 %0, %1, %2, %0;" : "+l"(d) : "l"(a), "l"(b));
}
__device__ __forceinline__ u64 pack2(float v) {
    unsigned u = __float_as_uint(v);
    return ((u64)u << 32) | u;
}

// ---------------------------------------------------------------------------
__global__ void k_init(const float* __restrict__ proto) {
    int j = threadIdx.x;  // 0..255
    float ss = 0.f;
#pragma unroll 8
    for (int k = 0; k < DD; k++) { float v = proto[j * DD + k]; ss += v * v; }
    float inv = __fdividef(1.f, fmaxf(sqrtf(ss), 1e-12f));
    for (int k = 0; k < DD; k++) g_ynT[k * KK + j] = proto[j * DD + k] * inv;
    const float nuP = 1.f / (float)KK + 1e-8f;
    g_T[0][j * 32] = nuP;   // makes w == 1 on iteration 1 (v0 = 0)
    g_T[1][j * 32] = 0.f;   // accumulation target of iteration 1
    if (j == 0) g_sum = 0.0;
}

// ---------------------------------------------------------------------------
__global__ void k_xnorm(const float* __restrict__ x) {
    int warp = threadIdx.x >> 5, lane = threadIdx.x & 31;
    int row = blockIdx.x * 8 + warp;
    float4 v = ((const float4*)(x + (size_t)row * DD))[lane];
    float ss = v.x * v.x + v.y * v.y + v.z * v.z + v.w * v.w;
#pragma unroll
    for (int o = 16; o; o >>= 1) ss += __shfl_xor_sync(0xffffffffu, ss, o);
    if (lane == 0) g_xinv[row] = __fdividef(1.f, fmaxf(sqrtf(ss), 1e-12f));
}

// ---------------------------------------------------------------------------
// cost GEMM via packed FFMA2: K' = exp(-10*(1 - xn.yn)) + 1e-8 (C not stored)
// block = 256 threads, 64 rows x 256 cols, 8x8 tile/thread (4 packed col-pairs)
// ---------------------------------------------------------------------------
__global__ void k_gemm(const float* __restrict__ x) {
    __shared__ float ys[32 * 256];  // k-chunk of prototypes [kk][col] (32KB)
    __shared__ u64 xs2[64 * 32];    // x tile, each value duplicated (16KB)

    int t = threadIdx.x;
    int rowBase = blockIdx.x * 64;
    int tx = t & 31, ty = t >> 5;

    u64 acc[8][4];
#pragma unroll
    for (int i = 0; i < 8; i++)
#pragma unroll
        for (int j = 0; j < 4; j++) acc[i][j] = 0ull;

    for (int kc = 0; kc < 4; kc++) {
        __syncthreads();
        {   // ys chunk (coalesced float4)
            const float4* src = (const float4*)(g_ynT + kc * 32 * 256);
            float4* dst = (float4*)ys;
#pragma unroll
            for (int i = 0; i < 8; i++) dst[t + i * 256] = src[t + i * 256];
        }
        {   // xs chunk, duplicated-packed
#pragma unroll
            for (int i = 0; i < 2; i++) {
                int idx = t + i * 256;       // float4 slot 0..511
                int r = idx >> 3;
                int c4 = idx & 7;
                float4 v = *(const float4*)(x + (size_t)(rowBase + r) * DD + kc * 32 + c4 * 4);
                u64* d = &xs2[r * 32 + c4 * 4];
                d[0] = pack2(v.x); d[1] = pack2(v.y); d[2] = pack2(v.z); d[3] = pack2(v.w);
            }
        }
        __syncthreads();
#pragma unroll 4
        for (int k = 0; k < 32; k++) {
            const ulonglong2* pb = (const ulonglong2*)&ys[k * 256 + tx * 8];
            ulonglong2 b01 = pb[0], b23 = pb[1];
#pragma unroll
            for (int i = 0; i < 8; i++) {
                u64 a2 = xs2[(ty * 8 + i) * 32 + k];   // broadcast LDS.64
                fma2(acc[i][0], a2, b01.x);
                fma2(acc[i][1], a2, b01.y);
                fma2(acc[i][2], a2, b23.x);
                fma2(acc[i][3], a2, b23.y);
            }
        }
    }

#pragma unroll
    for (int i = 0; i < 8; i++) {
        int row = rowBase + ty * 8 + i;
        float inv = g_xinv[row];
        float kv[8];
#pragma unroll
        for (int j = 0; j < 4; j++) {
            unsigned lo = (unsigned)(acc[i][j] & 0xffffffffull);
            unsigned hi = (unsigned)(acc[i][j] >> 32);
            float c0 = 1.f - __uint_as_float(lo) * inv;
            float c1 = 1.f - __uint_as_float(hi) * inv;
            kv[2 * j]     = __expf(-10.f * c0) + 1e-8f;
            kv[2 * j + 1] = __expf(-10.f * c1) + 1e-8f;
        }
        size_t base = (size_t)row * KK + tx * 8;
        *(float4*)&g_K[base]     = make_float4(kv[0], kv[1], kv[2], kv[3]);
        *(float4*)&g_K[base + 4] = make_float4(kv[4], kv[5], kv[6], kv[7]);
    }
}

// ---------------------------------------------------------------------------
// fused Sinkhorn iteration: w = nu'/T_prev ; a_i = mu'/(K' w)_i ; T_cur += K'^T a
// grid 1024 x 256; warp handles 8 rows (2-row load batches for MLP)
// ---------------------------------------------------------------------------
__global__ void k_iter(int prev, int cur, int clr) {
    const float nuP = 1.f / (float)KK + 1e-8f;
    const float muP = 1.f / (float)BB + 1e-8f;
    __shared__ float Ts2[8 * 256];

    int t = threadIdx.x, lane = t & 31, warp = t >> 5;
    if (blockIdx.x == 0) g_T[clr][t * 32] = 0.f;  // clear buffer for NEXT kernel

    float w[8];
#pragma unroll
    for (int m = 0; m < 4; m++) {
        w[m]     = nuP * __fdividef(1.f, g_T[prev][(lane * 4 + m) * 32]);
        w[4 + m] = nuP * __fdividef(1.f, g_T[prev][(128 + lane * 4 + m) * 32]);
    }

    float tj[8] = {0, 0, 0, 0, 0, 0, 0, 0};
    int rowBase = blockIdx.x * 64 + warp * 8;
#pragma unroll
    for (int rb = 0; rb < 8; rb += 2) {
        const float4* Kr0 = (const float4*)(g_K + (size_t)(rowBase + rb) * KK);
        const float4* Kr1 = (const float4*)(g_K + (size_t)(rowBase + rb + 1) * KK);
        float4 p0 = Kr0[lane], p1 = Kr0[32 + lane];
        float4 q0 = Kr1[lane], q1 = Kr1[32 + lane];
        float s0 = p0.x * w[0] + p0.y * w[1] + p0.z * w[2] + p0.w * w[3]
                 + p1.x * w[4] + p1.y * w[5] + p1.z * w[6] + p1.w * w[7];
        float s1 = q0.x * w[0] + q0.y * w[1] + q0.z * w[2] + q0.w * w[3]
                 + q1.x * w[4] + q1.y * w[5] + q1.z * w[6] + q1.w * w[7];
#pragma unroll
        for (int o = 16; o; o >>= 1) {
            s0 += __shfl_xor_sync(0xffffffffu, s0, o);
            s1 += __shfl_xor_sync(0xffffffffu, s1, o);
        }
        float a0 = muP * __fdividef(1.f, s0);
        float a1 = muP * __fdividef(1.f, s1);
        if (lane == 0) { g_a[rowBase + rb] = a0; g_a[rowBase + rb + 1] = a1; }
        tj[0] += p0.x * a0 + q0.x * a1; tj[1] += p0.y * a0 + q0.y * a1;
        tj[2] += p0.z * a0 + q0.z * a1; tj[3] += p0.w * a0 + q0.w * a1;
        tj[4] += p1.x * a0 + q1.x * a1; tj[5] += p1.y * a0 + q1.y * a1;
        tj[6] += p1.z * a0 + q1.z * a1; tj[7] += p1.w * a0 + q1.w * a1;
    }

#pragma unroll
    for (int m = 0; m < 4; m++) {
        Ts2[warp * 256 + lane * 4 + m] = tj[m];
        Ts2[warp * 256 + 128 + lane * 4 + m] = tj[4 + m];
    }
    __syncthreads();
    {
        float s = 0.f;
#pragma unroll
        for (int ww = 0; ww < 8; ww++) s += Ts2[ww * 256 + t];
        atomicAdd(&g_T[cur][t * 32], s);
    }
}

// ---------------------------------------------------------------------------
// final: sum_ij a_i * K'_ij * w_j * C_ij * softmax(|coord_i|)_j
// C recomputed from K':  C = -0.1 * log(K' - 1e-8)
// ---------------------------------------------------------------------------
__global__ void k_final(const float* __restrict__ coord, int cur) {
    const float nuP = 1.f / (float)KK + 1e-8f;
    int t = threadIdx.x, lane = t & 31, warp = t >> 5;

    float w[8];
#pragma unroll
    for (int m = 0; m < 4; m++) {
        w[m]     = nuP * __fdividef(1.f, g_T[cur][(lane * 4 + m) * 32]);
        w[4 + m] = nuP * __fdividef(1.f, g_T[cur][(128 + lane * 4 + m) * 32]);
    }

    float accf = 0.f;
    int rowBase = blockIdx.x * 64 + warp * 8;
#pragma unroll 2
    for (int r = 0; r < 8; r++) {
        int row = rowBase + r;
        const float4* Cd = (const float4*)(coord + (size_t)row * KK);
        float4 c0 = Cd[lane], c1 = Cd[32 + lane];
        float q[8] = {fabsf(c0.x), fabsf(c0.y), fabsf(c0.z), fabsf(c0.w),
                      fabsf(c1.x), fabsf(c1.y), fabsf(c1.z), fabsf(c1.w)};
        float mx = q[0];
#pragma unroll
        for (int m = 1; m < 8; m++) mx = fmaxf(mx, q[m]);
#pragma unroll
        for (int o = 16; o; o >>= 1) mx = fmaxf(mx, __shfl_xor_sync(0xffffffffu, mx, o));
        float e[8], z = 0.f;
#pragma unroll
        for (int m = 0; m < 8; m++) { e[m] = __expf(q[m] - mx); z += e[m]; }
#pragma unroll
        for (int o = 16; o; o >>= 1) z += __shfl_xor_sync(0xffffffffu, z, o);
        float rz = __fdividef(1.f, z);

        float a = g_a[row];
        const float4* Kr = (const float4*)(g_K + (size_t)row * KK);
        float4 k0 = Kr[lane], k1 = Kr[32 + lane];
        float kk[8] = {k0.x, k0.y, k0.z, k0.w, k1.x, k1.y, k1.z, k1.w};

        float contrib = 0.f;
#pragma unroll
        for (int m = 0; m < 8; m++) {
            float cm = -0.1f * __logf(kk[m] - 1e-8f);   // reconstruct C
            contrib += kk[m] * w[m] * cm * e[m];
        }
        accf += a * rz * contrib;
    }

#pragma unroll
    for (int o = 16; o; o >>= 1) accf += __shfl_xor_sync(0xffffffffu, accf, o);
    __shared__ double sw[8];
    if (lane == 0) sw[warp] = (double)accf;
    __syncthreads();
    if (t == 0) {
        double s = 0.0;
#pragma unroll
        for (int i = 0; i < 8; i++) s += sw[i];
        atomicAdd(&g_sum, s);
    }
}

__global__ void k_write(float* out) { out[0] = (float)g_sum; }

// ---------------------------------------------------------------------------
extern "C" void kernel_launch(void* const* d_in, const int* in_sizes, int n_in,
                              void* d_out, int out_size) {
    const float* x     = (const float*)d_in[0];   // (65536, 128)
    const float* proto = (const float*)d_in[1];   // (256, 128)
    const float* coord = (const float*)d_in[2];   // (65536, 256)

    k_init<<<1, 256>>>(proto);
    k_xnorm<<<BB / 8, 256>>>(x);
    k_gemm<<<BB / 64, 256>>>(x);

    for (int it = 1; it <= 50; it++)
        k_iter<<<1024, 256>>>((it - 1) % 3, it % 3, (it + 1) % 3);

    k_final<<<1024, 256>>>(coord, 50 % 3);
    k_write<<<1, 1>>>((float*)d_out);
}

// round 4
// speedup vs baseline: 1.4474x; 1.4474x over previous
#include <cuda_runtime.h>
#include <math.h>

#define BB 65536
#define KK 256
#define DD 128

typedef unsigned long long u64;

// ---- scratch (static device globals; no allocation) ----
__device__ float g_K[(size_t)BB * KK];   // K' = exp(-C/eps) + 1e-8  (64MB) — keep L2-resident
__device__ float g_ynT[DD * KK];         // normalized prototypes, k-major [k][j]
__device__ float g_xinv[BB];             // 1 / ||x_i||
__device__ float g_a[BB];                // exp(u)
__device__ float g_T[3][KK * 32];        // column sums, padded 128B apart
__device__ double g_sum;

// 256-bit L2-pinned load: 8 consecutive floats, biased to stay in L2
__device__ __forceinline__ void ld256_el(const float* p, float* v) {
    u64 a, b, c, d;
    asm volatile("ld.global.L2::evict_last.v4.b64 {%0,%1,%2,%3}, [%4];"
                 : "=l"(a), "=l"(b), "=l"(c), "=l"(d) : "l"(p));
    v[0] = __uint_as_float((unsigned)(a & 0xffffffffull));
    v[1] = __uint_as_float((unsigned)(a >> 32));
    v[2] = __uint_as_float((unsigned)(b & 0xffffffffull));
    v[3] = __uint_as_float((unsigned)(b >> 32));
    v[4] = __uint_as_float((unsigned)(c & 0xffffffffull));
    v[5] = __uint_as_float((unsigned)(c >> 32));
    v[6] = __uint_as_float((unsigned)(d & 0xffffffffull));
    v[7] = __uint_as_float((unsigned)(d >> 32));
}

// ---------------------------------------------------------------------------
__global__ void k_init(const float* __restrict__ proto) {
    int j = threadIdx.x;  // 0..255
    float ss = 0.f;
#pragma unroll 8
    for (int k = 0; k < DD; k++) { float v = proto[j * DD + k]; ss += v * v; }
    float inv = __fdividef(1.f, fmaxf(sqrtf(ss), 1e-12f));
    for (int k = 0; k < DD; k++) g_ynT[k * KK + j] = proto[j * DD + k] * inv;
    const float nuP = 1.f / (float)KK + 1e-8f;
    g_T[0][j * 32] = nuP;   // makes w == 1 on iteration 1 (v0 = 0)
    g_T[1][j * 32] = 0.f;   // accumulation target of iteration 1
    if (j == 0) g_sum = 0.0;
}

// ---------------------------------------------------------------------------
__global__ void k_xnorm(const float* __restrict__ x) {
    int warp = threadIdx.x >> 5, lane = threadIdx.x & 31;
    int row = blockIdx.x * 8 + warp;
    float4 v = ((const float4*)(x + (size_t)row * DD))[lane];
    float ss = v.x * v.x + v.y * v.y + v.z * v.z + v.w * v.w;
#pragma unroll
    for (int o = 16; o; o >>= 1) ss += __shfl_xor_sync(0xffffffffu, ss, o);
    if (lane == 0) g_xinv[row] = __fdividef(1.f, fmaxf(sqrtf(ss), 1e-12f));
}

// ---------------------------------------------------------------------------
// cost GEMM: K' = exp(-10*(1 - xn.yn)) + 1e-8
// block = 256 threads, 64 rows x 256 cols per block, 8x8 register tile/thread
// ---------------------------------------------------------------------------
__global__ void k_gemm(const float* __restrict__ x) {
    __shared__ float ys[32 * 256];  // k-chunk of prototypes [kk][col]  (32KB)
    __shared__ float xs[64 * 32];   // x tile [row][kk]                 (8KB)
    __shared__ float xrn[64];

    int t = threadIdx.x;
    int rowBase = blockIdx.x * 64;
    if (t < 64) xrn[t] = g_xinv[rowBase + t];

    int tx = t & 31, ty = t >> 5;
    float acc[8][8];
#pragma unroll
    for (int i = 0; i < 8; i++)
#pragma unroll
        for (int j = 0; j < 8; j++) acc[i][j] = 0.f;

    for (int kc = 0; kc < 4; kc++) {
        __syncthreads();
        {
            const float4* src = (const float4*)(g_ynT + kc * 32 * 256);
            float4* dst = (float4*)ys;
#pragma unroll
            for (int i = 0; i < 8; i++) dst[t + i * 256] = src[t + i * 256];
        }
        {
#pragma unroll
            for (int i = 0; i < 2; i++) {
                int idx = t + i * 256;
                int r = idx >> 3;
                int c4 = idx & 7;
                float4 v = *(const float4*)(x + (size_t)(rowBase + r) * DD + kc * 32 + c4 * 4);
                *(float4*)&xs[r * 32 + c4 * 4] = v;
            }
        }
        __syncthreads();
#pragma unroll 4
        for (int k = 0; k < 32; k++) {
            float4 b0 = *(const float4*)&ys[k * 256 + tx * 8];
            float4 b1 = *(const float4*)&ys[k * 256 + tx * 8 + 4];
#pragma unroll
            for (int i = 0; i < 8; i++) {
                float a = xs[(ty * 8 + i) * 32 + k];
                acc[i][0] += a * b0.x; acc[i][1] += a * b0.y;
                acc[i][2] += a * b0.z; acc[i][3] += a * b0.w;
                acc[i][4] += a * b1.x; acc[i][5] += a * b1.y;
                acc[i][6] += a * b1.z; acc[i][7] += a * b1.w;
            }
        }
    }

#pragma unroll
    for (int i = 0; i < 8; i++) {
        int row = rowBase + ty * 8 + i;
        float inv = xrn[ty * 8 + i];
        float kv[8];
#pragma unroll
        for (int j = 0; j < 8; j++) {
            float c = 1.f - acc[i][j] * inv;
            kv[j] = __expf(-10.f * c) + 1e-8f;
        }
        size_t base = (size_t)row * KK + tx * 8;
        *(float4*)&g_K[base]     = make_float4(kv[0], kv[1], kv[2], kv[3]);
        *(float4*)&g_K[base + 4] = make_float4(kv[4], kv[5], kv[6], kv[7]);
    }
}

// ---------------------------------------------------------------------------
// fused Sinkhorn iteration: w = nu'/T_prev ; a_i = mu'/(K' w)_i ; T_cur += K'^T a
// persistent grid 444 (148 SMs x 3 blocks); lane owns cols [8l..8l+7];
// 4-row batches -> 4 independent LDG.256 per lane in flight.
// ---------------------------------------------------------------------------
__global__ void __launch_bounds__(256, 3) k_iter(int prev, int cur, int clr) {
    const float nuP = 1.f / (float)KK + 1e-8f;
    const float muP = 1.f / (float)BB + 1e-8f;
    __shared__ float Ts2[8 * 256];

    int t = threadIdx.x, lane = t & 31, warp = t >> 5;
    if (blockIdx.x == 0) g_T[clr][t * 32] = 0.f;  // clear buffer for NEXT kernel

    float w[8];
#pragma unroll
    for (int m = 0; m < 8; m++)
        w[m] = nuP * __fdividef(1.f, g_T[prev][(lane * 8 + m) * 32]);

    float tj[8] = {0, 0, 0, 0, 0, 0, 0, 0};
    const int nWarps = 444 * 8;                 // 3552
    const int nBatch = BB / 4;                  // 16384 batches of 4 rows
    int gw = blockIdx.x * 8 + warp;
    int colOff = lane * 8;

    for (int b = gw; b < nBatch; b += nWarps) {
        int row0 = b * 4;
        const float* p = g_K + (size_t)row0 * KK + colOff;
        float r0[8], r1[8], r2[8], r3[8];
        ld256_el(p, r0);
        ld256_el(p + KK, r1);
        ld256_el(p + 2 * KK, r2);
        ld256_el(p + 3 * KK, r3);

        float s0 = 0.f, s1 = 0.f, s2 = 0.f, s3 = 0.f;
#pragma unroll
        for (int m = 0; m < 8; m++) {
            s0 += r0[m] * w[m]; s1 += r1[m] * w[m];
            s2 += r2[m] * w[m]; s3 += r3[m] * w[m];
        }
#pragma unroll
        for (int o = 16; o; o >>= 1) {
            s0 += __shfl_xor_sync(0xffffffffu, s0, o);
            s1 += __shfl_xor_sync(0xffffffffu, s1, o);
            s2 += __shfl_xor_sync(0xffffffffu, s2, o);
            s3 += __shfl_xor_sync(0xffffffffu, s3, o);
        }
        float a0 = muP * __fdividef(1.f, s0);
        float a1 = muP * __fdividef(1.f, s1);
        float a2 = muP * __fdividef(1.f, s2);
        float a3 = muP * __fdividef(1.f, s3);
        if (lane == 0) *(float4*)&g_a[row0] = make_float4(a0, a1, a2, a3);

#pragma unroll
        for (int m = 0; m < 8; m++)
            tj[m] += r0[m] * a0 + r1[m] * a1 + r2[m] * a2 + r3[m] * a3;
    }

#pragma unroll
    for (int m = 0; m < 8; m++)
        Ts2[warp * 256 + lane * 8 + m] = tj[m];
    __syncthreads();
    {
        float s = 0.f;
#pragma unroll
        for (int ww = 0; ww < 8; ww++) s += Ts2[ww * 256 + t];
        atomicAdd(&g_T[cur][t * 32], s);
    }
}

// ---------------------------------------------------------------------------
// final: sum_ij a_i * K'_ij * w_j * C_ij * softmax(|coord_i|)_j
// C reconstructed: C = -0.1 * log(K' - 1e-8). Persistent grid 444.
// ---------------------------------------------------------------------------
__global__ void __launch_bounds__(256, 3) k_final(const float* __restrict__ coord, int cur) {
    const float nuP = 1.f / (float)KK + 1e-8f;
    int t = threadIdx.x, lane = t & 31, warp = t >> 5;

    float w[8];
#pragma unroll
    for (int m = 0; m < 8; m++)
        w[m] = nuP * __fdividef(1.f, g_T[cur][(lane * 8 + m) * 32]);

    float accf = 0.f;
    const int nWarps = 444 * 8;
    const int nBatch = BB / 2;   // batches of 2 rows
    int gw = blockIdx.x * 8 + warp;
    int colOff = lane * 8;

    for (int b = gw; b < nBatch; b += nWarps) {
        int row0 = b * 2;
#pragma unroll
        for (int r = 0; r < 2; r++) {
            int row = row0 + r;
            float q[8];
            {
                const float4* Cd = (const float4*)(coord + (size_t)row * KK + colOff);
                float4 c0 = Cd[0], c1 = Cd[1];
                q[0] = fabsf(c0.x); q[1] = fabsf(c0.y); q[2] = fabsf(c0.z); q[3] = fabsf(c0.w);
                q[4] = fabsf(c1.x); q[5] = fabsf(c1.y); q[6] = fabsf(c1.z); q[7] = fabsf(c1.w);
            }
            float mx = q[0];
#pragma unroll
            for (int m = 1; m < 8; m++) mx = fmaxf(mx, q[m]);
#pragma unroll
            for (int o = 16; o; o >>= 1) mx = fmaxf(mx, __shfl_xor_sync(0xffffffffu, mx, o));
            float e[8], z = 0.f;
#pragma unroll
            for (int m = 0; m < 8; m++) { e[m] = __expf(q[m] - mx); z += e[m]; }
#pragma unroll
            for (int o = 16; o; o >>= 1) z += __shfl_xor_sync(0xffffffffu, z, o);
            float rz = __fdividef(1.f, z);

            float a = g_a[row];
            float kk[8];
            ld256_el(g_K + (size_t)row * KK + colOff, kk);

            float contrib = 0.f;
#pragma unroll
            for (int m = 0; m < 8; m++) {
                float cm = -0.1f * __logf(kk[m] - 1e-8f);   // reconstruct C
                contrib += kk[m] * w[m] * cm * e[m];
            }
            accf += a * rz * contrib;
        }
    }

#pragma unroll
    for (int o = 16; o; o >>= 1) accf += __shfl_xor_sync(0xffffffffu, accf, o);
    __shared__ double sw[8];
    if (lane == 0) sw[warp] = (double)accf;
    __syncthreads();
    if (t == 0) {
        double s = 0.0;
#pragma unroll
        for (int i = 0; i < 8; i++) s += sw[i];
        atomicAdd(&g_sum, s);
    }
}

__global__ void k_write(float* out) { out[0] = (float)g_sum; }

// ---------------------------------------------------------------------------
extern "C" void kernel_launch(void* const* d_in, const int* in_sizes, int n_in,
                              void* d_out, int out_size) {
    const float* x     = (const float*)d_in[0];   // (65536, 128)
    const float* proto = (const float*)d_in[1];   // (256, 128)
    const float* coord = (const float*)d_in[2];   // (65536, 256)

    k_init<<<1, 256>>>(proto);
    k_xnorm<<<BB / 8, 256>>>(x);
    k_gemm<<<BB / 64, 256>>>(x);

    for (int it = 1; it <= 50; it++)
        k_iter<<<444, 256>>>((it - 1) % 3, it % 3, (it + 1) % 3);

    k_final<<<444, 256>>>(coord, 50 % 3);
    k_write<<<1, 1>>>((float*)d_out);
}